// round 10
// baseline (speedup 1.0000x reference)
#include <cuda_runtime.h>
#include <cuda_bf16.h>
#include <cstdint>

// Decoder (Conv-TasNet): out = overlap_add( (mixture_w * est_mask)^T @ W^T, step=L/2 )
// mixture_w/est_mask [B, N, K] f32, W [L, N] f32, out [B, T] f32
// B=4, N=512, K=16000, L=16, step=8, T = 8*(K-1)+16 = 128008
//
// R10 = R9 datapath (KPT=4, LDG.128, FFMA2) with NSPLIT=8 so the grid is big
// enough to reach the register-allowed occupancy (R9 was grid-starved at
// 6.8 blocks/SM; 86 regs x 64 thr allows 11).

#define DEC_B 4
#define DEC_N 512
#define DEC_K 16000
#define DEC_L 16
#define DEC_STEP 8
#define DEC_T (DEC_STEP * (DEC_K - 1) + DEC_L)   // 128008

#define TPB 64
#define NSPLIT 8
#define NCHUNK (DEC_N / NSPLIT)      // 64
#define KPT 4                         // frames per thread (float4 along k)
#define NB 4                          // n's per load batch (8 LDG.128 in flight)
#define NACC 20                       // f32x2 accumulators (40 out positions)

typedef unsigned long long u64t;

#define FMA_F32X2(d, a, b, c) \
    asm("fma.rn.f32x2 %0, %1, %2, %3;" : "=l"(d) : "l"(a), "l"(b), "l"(c))

__global__ __launch_bounds__(TPB)
void decoder_kernel(const float* __restrict__ mw,
                    const float* __restrict__ em,
                    const float* __restrict__ W,
                    float* __restrict__ out)
{
    // This block's N-chunk of W, transposed: Ws[n_local][l]. 4 KB.
    __shared__ __align__(16) float Ws[NCHUNK * DEC_L];
    const int nb = blockIdx.z * NCHUNK;
    for (int i = threadIdx.x; i < NCHUNK * DEC_L; i += TPB) {
        int n = i >> 4;
        int l = i & 15;
        Ws[i] = W[l * DEC_N + nb + n];
    }
    __syncthreads();

    const int b  = blockIdx.y;
    const int k0 = (blockIdx.x * TPB + threadIdx.x) * KPT;
    if (k0 >= DEC_K) return;   // tail guard (63*64*4 = 16128 > 16000; K%4==0)

    const size_t base = (size_t)b * DEC_N * DEC_K + (size_t)nb * DEC_K + k0;
    const float4* __restrict__ mwp = reinterpret_cast<const float4*>(mw + base);
    const float4* __restrict__ emp = reinterpret_cast<const float4*>(em + base);
    const size_t kstr = DEC_K / 4;   // float4 stride between n rows

    // 40 fp32 out positions as 20 f32x2 pairs. Frame fi (i=0..3) covers
    // positions 8i..8i+15 = pairs 4i..4i+7.
    u64t accp[NACC];
#pragma unroll
    for (int i = 0; i < NACC; ++i) accp[i] = 0ull;

    // One n-step: 4 FMUL + 4 packs + 4 LDS.128 + 32 FFMA2, serving 4 frames.
    auto step = [&](int n, float4 m, float4 e) {
        float p[KPT];
        p[0] = m.x * e.x;
        p[1] = m.y * e.y;
        p[2] = m.z * e.z;
        p[3] = m.w * e.w;
        u64t pp[KPT];
#pragma unroll
        for (int f = 0; f < KPT; ++f)
            asm("mov.b64 %0, {%1, %1};" : "=l"(pp[f]) : "f"(p[f]));

        const ulonglong2* wq = reinterpret_cast<const ulonglong2*>(&Ws[n * DEC_L]);
        ulonglong2 wa = wq[0];
        ulonglong2 wb = wq[1];
        ulonglong2 wc = wq[2];
        ulonglong2 wd = wq[3];
        u64t w[8] = { wa.x, wa.y, wb.x, wb.y, wc.x, wc.y, wd.x, wd.y };

#pragma unroll
        for (int f = 0; f < KPT; ++f) {
#pragma unroll
            for (int j = 0; j < 8; ++j) {
                FMA_F32X2(accp[4 * f + j], w[j], pp[f], accp[4 * f + j]);
            }
        }
    };

    for (int n0 = 0; n0 < NCHUNK; n0 += NB) {
        // Batch: 8 independent coalesced streaming LDG.128s (32 lines in flight).
        float4 m[NB], e[NB];
#pragma unroll
        for (int j = 0; j < NB; ++j) {
            m[j] = __ldcs(&mwp[(size_t)(n0 + j) * kstr]);
            e[j] = __ldcs(&emp[(size_t)(n0 + j) * kstr]);
        }
#pragma unroll
        for (int j = 0; j < NB; ++j) step(n0 + j, m[j], e[j]);
    }

    // Scatter-add 40 unique positions (frames k0..k0+3). Interior overlaps
    // merged in registers; each out element gets <= 2*NSPLIT = 16 atomic fp32
    // contributions (order-insensitive).
    float* __restrict__ op = out + (size_t)b * DEC_T + (size_t)k0 * DEC_STEP;
#pragma unroll
    for (int i = 0; i < NACC; ++i) {
        float lo, hi;
        asm("mov.b64 {%0, %1}, %2;" : "=f"(lo), "=f"(hi) : "l"(accp[i]));
        atomicAdd(&op[2 * i],     lo);
        atomicAdd(&op[2 * i + 1], hi);
    }
}

extern "C" void kernel_launch(void* const* d_in, const int* in_sizes, int n_in,
                              void* d_out, int out_size)
{
    const float* mixture_w = (const float*)d_in[0];  // [B, N, K]
    const float* est_mask  = (const float*)d_in[1];  // [B, N, K]
    const float* W         = (const float*)d_in[2];  // [L, N]
    float* out = (float*)d_out;                       // [B, T]

    cudaMemsetAsync(out, 0, (size_t)out_size * sizeof(float), 0);

    dim3 grid((DEC_K + TPB * KPT - 1) / (TPB * KPT), DEC_B, NSPLIT);  // (63, 4, 8)
    decoder_kernel<<<grid, TPB>>>(mixture_w, est_mask, W, out);
}

// round 11
// speedup vs baseline: 1.1086x; 1.1086x over previous
#include <cuda_runtime.h>
#include <cuda_bf16.h>
#include <cstdint>

// Decoder (Conv-TasNet): out = overlap_add( (mixture_w * est_mask)^T @ W^T, step=L/2 )
// mixture_w/est_mask [B, N, K] f32, W [L, N] f32, out [B, T] f32
// B=4, N=512, K=16000, L=16, step=8, T = 8*(K-1)+16 = 128008
//
// R11: KPT=4 datapath (best measured per-warp BW) at single-wave geometry.
// TPB=128, NSPLIT=8 -> grid 1024 = 6.92 blocks/SM; __launch_bounds__(128,7)
// pins regs <= 73 so 7 blocks (28 warps/SM) fit in ONE wave. Register diet:
// quarter-wise W reads (4 live W regs), 32-bit indexing, NB=2 batches.

#define DEC_B 4
#define DEC_N 512
#define DEC_K 16000
#define DEC_L 16
#define DEC_STEP 8
#define DEC_T (DEC_STEP * (DEC_K - 1) + DEC_L)   // 128008

#define TPB 128
#define NSPLIT 8
#define NCHUNK (DEC_N / NSPLIT)      // 64
#define KPT 4                         // frames per thread (float4 along k)
#define NACC 20                       // f32x2 accumulators (40 out positions)

typedef unsigned long long u64t;

#define FMA_F32X2(d, a, b, c) \
    asm("fma.rn.f32x2 %0, %1, %2, %3;" : "=l"(d) : "l"(a), "l"(b), "l"(c))

__global__ __launch_bounds__(TPB, 7)
void decoder_kernel(const float* __restrict__ mw,
                    const float* __restrict__ em,
                    const float* __restrict__ W,
                    float* __restrict__ out)
{
    // This block's N-chunk of W, transposed: Ws[n_local][l]. 4 KB.
    __shared__ __align__(16) float Ws[NCHUNK * DEC_L];
    const int nb = blockIdx.z * NCHUNK;
    for (int i = threadIdx.x; i < NCHUNK * DEC_L; i += TPB) {
        int n = i >> 4;
        int l = i & 15;
        Ws[i] = W[l * DEC_N + nb + n];
    }
    __syncthreads();

    const int b  = blockIdx.y;
    const int k0 = (blockIdx.x * TPB + threadIdx.x) * KPT;
    if (k0 >= DEC_K) return;   // grid.x*TPB*KPT = 16384 > 16000; K%4==0

    // 32-bit indexing: total input floats = 32.77M < 2^31.
    const float4* __restrict__ mw4 = reinterpret_cast<const float4*>(mw);
    const float4* __restrict__ em4 = reinterpret_cast<const float4*>(em);
    unsigned idx = ((unsigned)b * (DEC_N * DEC_K) + (unsigned)nb * DEC_K + (unsigned)k0) >> 2;
    const unsigned kstr = DEC_K / 4;   // float4 stride between n rows

    // 40 fp32 out positions as 20 f32x2 pairs. Frame f (0..3) covers
    // positions 8f..8f+15 = pairs 4f..4f+7.
    u64t accp[NACC];
#pragma unroll
    for (int i = 0; i < NACC; ++i) accp[i] = 0ull;

    // One n-step: 4 FMUL + 4 packs + 4 LDS.128 (quarter-wise, 4 live W regs)
    // + 32 FFMA2, serving 4 frames.
    auto step = [&](int n, float4 m, float4 e) {
        float p0 = m.x * e.x;
        float p1 = m.y * e.y;
        float p2 = m.z * e.z;
        float p3 = m.w * e.w;
        u64t pp[KPT];
        asm("mov.b64 %0, {%1, %1};" : "=l"(pp[0]) : "f"(p0));
        asm("mov.b64 %0, {%1, %1};" : "=l"(pp[1]) : "f"(p1));
        asm("mov.b64 %0, {%1, %1};" : "=l"(pp[2]) : "f"(p2));
        asm("mov.b64 %0, {%1, %1};" : "=l"(pp[3]) : "f"(p3));

        const ulonglong2* wq = reinterpret_cast<const ulonglong2*>(&Ws[n * DEC_L]);
#pragma unroll
        for (int q = 0; q < 4; ++q) {
            ulonglong2 w2 = wq[q];      // pairs j = 2q, 2q+1
#pragma unroll
            for (int f = 0; f < KPT; ++f) {
                FMA_F32X2(accp[4 * f + 2 * q],     w2.x, pp[f], accp[4 * f + 2 * q]);
                FMA_F32X2(accp[4 * f + 2 * q + 1], w2.y, pp[f], accp[4 * f + 2 * q + 1]);
            }
        }
    };

#pragma unroll 2
    for (int n0 = 0; n0 < NCHUNK; n0 += 2) {
        // Batch: 4 independent coalesced streaming LDG.128s (16 lines in flight).
        float4 m0 = __ldcs(&mw4[idx]);
        float4 e0 = __ldcs(&em4[idx]);
        float4 m1 = __ldcs(&mw4[idx + kstr]);
        float4 e1 = __ldcs(&em4[idx + kstr]);
        idx += 2 * kstr;
        step(n0,     m0, e0);
        step(n0 + 1, m1, e1);
    }

    // Scatter-add 40 unique positions (frames k0..k0+3). Interior overlaps
    // merged in registers; <= 2*NSPLIT = 16 atomic fp32 contributions per
    // output element (order-insensitive).
    float* __restrict__ op = out + (unsigned)b * DEC_T + (unsigned)k0 * DEC_STEP;
#pragma unroll
    for (int i = 0; i < NACC; ++i) {
        float lo, hi;
        asm("mov.b64 {%0, %1}, %2;" : "=f"(lo), "=f"(hi) : "l"(accp[i]));
        atomicAdd(&op[2 * i],     lo);
        atomicAdd(&op[2 * i + 1], hi);
    }
}

extern "C" void kernel_launch(void* const* d_in, const int* in_sizes, int n_in,
                              void* d_out, int out_size)
{
    const float* mixture_w = (const float*)d_in[0];  // [B, N, K]
    const float* est_mask  = (const float*)d_in[1];  // [B, N, K]
    const float* W         = (const float*)d_in[2];  // [L, N]
    float* out = (float*)d_out;                       // [B, T]

    cudaMemsetAsync(out, 0, (size_t)out_size * sizeof(float), 0);

    dim3 grid((DEC_K + TPB * KPT - 1) / (TPB * KPT), DEC_B, NSPLIT);  // (32, 4, 8)
    decoder_kernel<<<grid, TPB>>>(mixture_w, est_mask, W, out);
}

// round 12
// speedup vs baseline: 1.3285x; 1.1983x over previous
#include <cuda_runtime.h>
#include <cuda_bf16.h>
#include <cstdint>

// Decoder (Conv-TasNet): out = overlap_add( (mixture_w * est_mask)^T @ W^T, step=L/2 )
// mixture_w/est_mask [B, N, K] f32, W [L, N] f32, out [B, T] f32
// B=4, N=512, K=16000, L=16, step=8, T = 8*(K-1)+16 = 128008
//
// R12 = R7 (best: 61.5us) with the load batch deepened to NB=8 and pinned
// with asm volatile so ptxas cannot sink the LDGs into the compute phase
// (the R8 failure mode). 16 independent LDG.64 in flight = 4KB/warp; the
// measured per-warp-BW ~ in-flight-bytes law says this is the binding lever.

#define DEC_B 4
#define DEC_N 512
#define DEC_K 16000
#define DEC_L 16
#define DEC_STEP 8
#define DEC_T (DEC_STEP * (DEC_K - 1) + DEC_L)   // 128008

#define TPB 128
#define NSPLIT 4
#define NCHUNK (DEC_N / NSPLIT)      // 128
#define KPT 2                         // frames per thread (float2 along k)
#define NB 8                          // n's per load batch (16 LDG.64 in flight)
#define NACC 12                       // f32x2 accumulators (24 out positions)

typedef unsigned long long u64t;

#define FMA_F32X2(d, a, b, c) \
    asm("fma.rn.f32x2 %0, %1, %2, %3;" : "=l"(d) : "l"(a), "l"(b), "l"(c))

// Volatile streaming 8-byte load: ordered against other volatile asm, so the
// whole 16-load batch is issued before the dependent compute phase.
#define LDG64_CS(v, p) \
    asm volatile("ld.global.cs.v2.f32 {%0, %1}, [%2];" \
                 : "=f"((v).x), "=f"((v).y) : "l"(p))

__global__ __launch_bounds__(TPB)
void decoder_kernel(const float* __restrict__ mw,
                    const float* __restrict__ em,
                    const float* __restrict__ W,
                    float* __restrict__ out)
{
    // This block's N-chunk of W, transposed: Ws[n_local][l]. 8 KB.
    __shared__ __align__(16) float Ws[NCHUNK * DEC_L];
    const int nb = blockIdx.z * NCHUNK;
    for (int i = threadIdx.x; i < NCHUNK * DEC_L; i += TPB) {
        int n = i >> 4;
        int l = i & 15;
        Ws[i] = W[l * DEC_N + nb + n];
    }
    __syncthreads();

    const int b  = blockIdx.y;
    const int k0 = (blockIdx.x * TPB + threadIdx.x) * KPT;
    if (k0 >= DEC_K) return;   // tail guard (63*128*2 = 16128 > 16000)

    const size_t base = (size_t)b * DEC_N * DEC_K + (size_t)nb * DEC_K + k0;
    const float* __restrict__ mwp = mw + base;
    const float* __restrict__ emp = em + base;

    // 24 fp32 accumulators as 12 x f32x2. Frame k0 -> accp[0..7],
    // frame k0+1 -> accp[4..11] (overlap of 8 positions = 4 pairs).
    u64t accp[NACC];
#pragma unroll
    for (int i = 0; i < NACC; ++i) accp[i] = 0ull;

    // One n-step: 2 FMUL + 2 packs + 4 LDS.128 + 16 FFMA2.
    auto step = [&](int n, float2 m, float2 e) {
        float p0 = m.x * e.x;
        float p1 = m.y * e.y;
        u64t pp0, pp1;
        asm("mov.b64 %0, {%1, %1};" : "=l"(pp0) : "f"(p0));
        asm("mov.b64 %0, {%1, %1};" : "=l"(pp1) : "f"(p1));

        const ulonglong2* w = reinterpret_cast<const ulonglong2*>(&Ws[n * DEC_L]);
        ulonglong2 w0 = w[0];
        ulonglong2 w1 = w[1];
        ulonglong2 w2 = w[2];
        ulonglong2 w3 = w[3];

        FMA_F32X2(accp[0],  w0.x, pp0, accp[0]);
        FMA_F32X2(accp[1],  w0.y, pp0, accp[1]);
        FMA_F32X2(accp[2],  w1.x, pp0, accp[2]);
        FMA_F32X2(accp[3],  w1.y, pp0, accp[3]);
        FMA_F32X2(accp[4],  w2.x, pp0, accp[4]);
        FMA_F32X2(accp[5],  w2.y, pp0, accp[5]);
        FMA_F32X2(accp[6],  w3.x, pp0, accp[6]);
        FMA_F32X2(accp[7],  w3.y, pp0, accp[7]);
        FMA_F32X2(accp[4],  w0.x, pp1, accp[4]);
        FMA_F32X2(accp[5],  w0.y, pp1, accp[5]);
        FMA_F32X2(accp[6],  w1.x, pp1, accp[6]);
        FMA_F32X2(accp[7],  w1.y, pp1, accp[7]);
        FMA_F32X2(accp[8],  w2.x, pp1, accp[8]);
        FMA_F32X2(accp[9],  w2.y, pp1, accp[9]);
        FMA_F32X2(accp[10], w3.x, pp1, accp[10]);
        FMA_F32X2(accp[11], w3.y, pp1, accp[11]);
    };

#pragma unroll 1
    for (int n0 = 0; n0 < NCHUNK; n0 += NB) {
        // Batch: 16 independent coalesced streaming LDG.64s, volatile-pinned
        // ahead of the compute phase (4KB in flight per warp).
        float2 m[NB], e[NB];
#pragma unroll
        for (int j = 0; j < NB; ++j) {
            LDG64_CS(m[j], mwp + (size_t)(n0 + j) * DEC_K);
            LDG64_CS(e[j], emp + (size_t)(n0 + j) * DEC_K);
        }
#pragma unroll
        for (int j = 0; j < NB; ++j) step(n0 + j, m[j], e[j]);
    }

    // Scatter-add 24 unique positions (frames k0, k0+1). <= 2*NSPLIT = 8 fp32
    // contributions per output element (atomic, order-insensitive).
    float* __restrict__ op = out + (size_t)b * DEC_T + (size_t)k0 * DEC_STEP;
#pragma unroll
    for (int i = 0; i < NACC; ++i) {
        float lo, hi;
        asm("mov.b64 {%0, %1}, %2;" : "=f"(lo), "=f"(hi) : "l"(accp[i]));
        atomicAdd(&op[2 * i],     lo);
        atomicAdd(&op[2 * i + 1], hi);
    }
}

extern "C" void kernel_launch(void* const* d_in, const int* in_sizes, int n_in,
                              void* d_out, int out_size)
{
    const float* mixture_w = (const float*)d_in[0];  // [B, N, K]
    const float* est_mask  = (const float*)d_in[1];  // [B, N, K]
    const float* W         = (const float*)d_in[2];  // [L, N]
    float* out = (float*)d_out;                       // [B, T]

    cudaMemsetAsync(out, 0, (size_t)out_size * sizeof(float), 0);

    dim3 grid((DEC_K + TPB * KPT - 1) / (TPB * KPT), DEC_B, NSPLIT);  // (63, 4, 4)
    decoder_kernel<<<grid, TPB>>>(mixture_w, est_mask, W, out);
}